// round 8
// baseline (speedup 1.0000x reference)
#include <cuda_runtime.h>

// LightGCN embedding propagation (out = (emb + x1 + x2 + x3)/4,
// x_{k+1}[d] = sum_{e:dst=d} dinv[src]*dinv[dst] * x_k[src]).
//
// Robustness: the harness may deliver edge_index as int32 OR int64, and the
// two inputs (emb: 6.4M f32, edge_index: 6.4M elems) are indistinguishable by
// element count. A device-side detect kernel resolves both (which input is
// the edge list, and its width) with no host sync, keeping graph capture legal.

static const int N_NODES = 100000;
static const int N_EDGES = 3200000;
static const int SCAN_B  = 256;
static const int NBLK    = (N_NODES + SCAN_B - 1) / SCAN_B;  // 391

// ---- scratch (__device__ globals; allocation is forbidden) ----
__device__ int   g_flags[2];        // [0] = which input is edge_index, [1] = is64
__device__ int   g_src[N_EDGES];
__device__ int   g_dst[N_EDGES];
__device__ int   g_deg[N_NODES];
__device__ int   g_rowptr[N_NODES];
__device__ int   g_cursor[N_NODES];
__device__ float g_dinv[N_NODES];
__device__ int   g_bsum[512];
__device__ int   g_srcs[N_EDGES];
__device__ float g_w[N_EDGES];
__device__ float g_x0[N_NODES * 64];
__device__ float g_x1[N_NODES * 64];

// ---- input-ABI detection -------------------------------------------------
// Sample the first 128 edge slots (first 1KB — in bounds for every layout).
// int64 edges: even words in [0,N), odd words == 0.
// int32 edges: all words in [0,N).
// float emb:   bit patterns ~1e9 / negative -> fails both tests.
__global__ void k_detect(const int* __restrict__ a, const int* __restrict__ b) {
    if (blockIdx.x != 0 || threadIdx.x != 0) return;
    const int* cand[2] = {a, b};
    int which = 1, is64 = 1;  // fallback: input 1, int64 (natural layout)
    for (int c = 0; c < 2; c++) {
        const int* p = cand[c];
        bool ok64 = true, ok32 = true;
        for (int e = 0; e < 128; e++) {
            int lo = p[2 * e], hi = p[2 * e + 1];
            if (hi != 0 || lo < 0 || lo >= N_NODES) ok64 = false;
            if (lo < 0 || lo >= N_NODES || hi < 0 || hi >= N_NODES) ok32 = false;
        }
        if (ok64) { which = c; is64 = 1; break; }
        if (ok32) { which = c; is64 = 0; break; }
    }
    g_flags[0] = which;
    g_flags[1] = is64;
}

// Canonicalize edge_index into int32 g_src/g_dst (clamped defensively).
__global__ void k_convert(const int* __restrict__ a, const int* __restrict__ b) {
    int e = blockIdx.x * blockDim.x + threadIdx.x;
    if (e >= N_EDGES) return;
    const int* p = g_flags[0] ? b : a;
    int s, d;
    if (g_flags[1]) {            // int64: take low words
        s = p[2 * e];
        d = p[2 * (e + N_EDGES)];
    } else {                     // int32
        s = p[e];
        d = p[e + N_EDGES];
    }
    s = min(max(s, 0), N_NODES - 1);
    d = min(max(d, 0), N_NODES - 1);
    g_src[e] = s;
    g_dst[e] = d;
}

// ---- CSR build -----------------------------------------------------------
__global__ void k_zero() {
    int i = blockIdx.x * blockDim.x + threadIdx.x;
    if (i < N_NODES) { g_deg[i] = 0; g_cursor[i] = 0; }
}

__global__ void k_hist() {
    int e = blockIdx.x * blockDim.x + threadIdx.x;
    if (e < N_EDGES) atomicAdd(&g_deg[g_dst[e]], 1);
}

__global__ void k_dinv() {
    int i = blockIdx.x * blockDim.x + threadIdx.x;
    if (i < N_NODES) {
        int d = g_deg[i];
        g_dinv[i] = (d > 0) ? rsqrtf((float)d) : 0.0f;
    }
}

// Block-local exclusive scan of g_deg -> g_rowptr; block totals -> g_bsum.
__global__ void k_scan_local() {
    __shared__ int wsum[8];
    int i = blockIdx.x * SCAN_B + threadIdx.x;
    int v = (i < N_NODES) ? g_deg[i] : 0;
    int lane = threadIdx.x & 31, wid = threadIdx.x >> 5;
    int x = v;
#pragma unroll
    for (int o = 1; o < 32; o <<= 1) {
        int y = __shfl_up_sync(0xffffffffu, x, o);
        if (lane >= o) x += y;
    }
    if (lane == 31) wsum[wid] = x;
    __syncthreads();
    if (wid == 0) {
        int s = (lane < 8) ? wsum[lane] : 0;
#pragma unroll
        for (int o = 1; o < 8; o <<= 1) {
            int y = __shfl_up_sync(0xffffffffu, s, o);
            if (lane >= o) s += y;
        }
        if (lane < 8) wsum[lane] = s;
    }
    __syncthreads();
    int incl = x + (wid > 0 ? wsum[wid - 1] : 0);
    if (i < N_NODES) g_rowptr[i] = incl - v;
    if (threadIdx.x == SCAN_B - 1) g_bsum[blockIdx.x] = incl;
}

// Single-block exclusive scan of the 391 block totals.
__global__ void k_scan_bsum(int nb) {
    __shared__ int ws[16];
    int i = threadIdx.x;
    int v = (i < nb) ? g_bsum[i] : 0;
    int lane = i & 31, wid = i >> 5;
    int x = v;
#pragma unroll
    for (int o = 1; o < 32; o <<= 1) {
        int y = __shfl_up_sync(0xffffffffu, x, o);
        if (lane >= o) x += y;
    }
    if (lane == 31) ws[wid] = x;
    __syncthreads();
    if (wid == 0) {
        int s = (lane < 16) ? ws[lane] : 0;
#pragma unroll
        for (int o = 1; o < 16; o <<= 1) {
            int y = __shfl_up_sync(0xffffffffu, s, o);
            if (lane >= o) s += y;
        }
        if (lane < 16) ws[lane] = s;
    }
    __syncthreads();
    int excl = x - v + (wid > 0 ? ws[wid - 1] : 0);
    if (i < nb) g_bsum[i] = excl;
}

__global__ void k_scan_add() {
    int i = blockIdx.x * blockDim.x + threadIdx.x;
    if (i < N_NODES) g_rowptr[i] += g_bsum[i >> 8];  // SCAN_B == 256
}

__global__ void k_scatter() {
    int e = blockIdx.x * blockDim.x + threadIdx.x;
    if (e < N_EDGES) {
        int s = g_src[e];
        int d = g_dst[e];
        int pos = g_rowptr[d] + atomicAdd(&g_cursor[d], 1);
        g_srcs[pos] = s;
        g_w[pos]    = g_dinv[s] * g_dinv[d];
    }
}

// ---- epilogue init: out = emb / 4 ----------------------------------------
__global__ void k_init_out(const float4* __restrict__ a,
                           const float4* __restrict__ b,
                           float4* __restrict__ out) {
    int i = blockIdx.x * blockDim.x + threadIdx.x;
    if (i >= N_NODES * 16) return;
    const float4* emb = g_flags[0] ? a : b;  // emb = the NON-edge input
    float4 v = emb[i];
    out[i] = make_float4(0.25f * v.x, 0.25f * v.y, 0.25f * v.z, 0.25f * v.w);
}

// ---- SpMM: warp per destination row, lane l owns dims [2l,2l+1] ----------
// Edge (idx,w) pairs staged 32-wide through shared memory; LDS same-address
// reads broadcast conflict-free. No atomics: one warp owns each output row.
// layer 0: xin = emb, xout = g_x0; layer 1: g_x0 -> g_x1; layer 2: g_x1 -> (none).
__global__ void k_spmm(const float2* __restrict__ a,
                       const float2* __restrict__ b,
                       float2* __restrict__ out, int layer) {
    __shared__ int   sh_i[8][32];
    __shared__ float sh_w[8][32];
    int wl   = threadIdx.x >> 5;
    int lane = threadIdx.x & 31;
    int row  = blockIdx.x * 8 + wl;
    if (row >= N_NODES) return;

    const float2* xin;
    float2* xout;
    if (layer == 0)      { xin = g_flags[0] ? a : b;      xout = (float2*)g_x0; }
    else if (layer == 1) { xin = (const float2*)g_x0;     xout = (float2*)g_x1; }
    else                 { xin = (const float2*)g_x1;     xout = nullptr;       }

    int start = g_rowptr[row];
    int cnt   = g_deg[row];
    float ax = 0.0f, ay = 0.0f;

    for (int base = 0; base < cnt; base += 32) {
        int rem = cnt - base;
        int m = rem < 32 ? rem : 32;
        if (lane < m) {
            sh_i[wl][lane] = g_srcs[start + base + lane];
            sh_w[wl][lane] = g_w[start + base + lane];
        }
        __syncwarp();
#pragma unroll 4
        for (int j = 0; j < m; j++) {
            int   s = sh_i[wl][j];
            float w = sh_w[wl][j];
            float2 v = __ldg(&xin[s * 32 + lane]);
            ax = fmaf(w, v.x, ax);
            ay = fmaf(w, v.y, ay);
        }
        __syncwarp();
    }

    int o = row * 32 + lane;
    if (xout) xout[o] = make_float2(ax, ay);
    float2 po = out[o];
    out[o] = make_float2(fmaf(0.25f, ax, po.x), fmaf(0.25f, ay, po.y));
}

extern "C" void kernel_launch(void* const* d_in, const int* in_sizes, int n_in,
                              void* d_out, int out_size) {
    const void* p0 = d_in[0];
    const void* p1 = d_in[1];
    float* out = (float*)d_out;

    const int T  = 256;
    const int gN = (N_NODES + T - 1) / T;
    const int gE = (N_EDGES + T - 1) / T;

    // Resolve input ABI (which input is edge_index; int32 vs int64), then
    // canonicalize edges to int32 g_src/g_dst. All device-side, graph-safe.
    k_detect <<<1, 32>>>((const int*)p0, (const int*)p1);
    k_convert<<<gE, T>>>((const int*)p0, (const int*)p1);

    // Build CSR-by-dst + symmetric-norm weights.
    k_zero      <<<gN, T>>>();
    k_hist      <<<gE, T>>>();
    k_dinv      <<<gN, T>>>();
    k_scan_local<<<NBLK, SCAN_B>>>();
    k_scan_bsum <<<1, 512>>>(NBLK);
    k_scan_add  <<<gN, T>>>();
    k_scatter   <<<gE, T>>>();

    // out = emb/4, then 3 propagation layers each adding x_k/4.
    k_init_out<<<(N_NODES * 16 + T - 1) / T, T>>>((const float4*)p0, (const float4*)p1,
                                                  (float4*)out);
    const int gS = (N_NODES + 7) / 8;  // 8 rows (warps) per 256-thread block
    k_spmm<<<gS, T>>>((const float2*)p0, (const float2*)p1, (float2*)out, 0);
    k_spmm<<<gS, T>>>((const float2*)p0, (const float2*)p1, (float2*)out, 1);
    k_spmm<<<gS, T>>>((const float2*)p0, (const float2*)p1, (float2*)out, 2);
}

// round 9
// speedup vs baseline: 1.2872x; 1.2872x over previous
#include <cuda_runtime.h>
#include <cuda_fp16.h>

// LightGCN embedding propagation (out = (emb + x1 + x2 + x3)/4,
// x_{k+1}[d] = sum_{e:dst=d} dinv[src]*dinv[dst] * x_k[src]).
//
// R9: L2-bandwidth-bound -> cut bytes.
//  - fp16 feature storage for all gathered operands (emb_h, x0_h, x1_h);
//    f32 accumulation; out stays f32 and always receives the f32 accumulator,
//    so fp16 rounding only enters via the (small) propagated terms.
//  - no edge-index conversion pass: hist/scatter read the detected input
//    buffer (int32 or int64) directly.
//  - (src, w) interleaved as one int2 per edge: 1 LDG.64 / STG.64.
//  - init (out = emb/4) fused into spmm layer 0.

static const int N_NODES = 100000;
static const int N_EDGES = 3200000;
static const int SCAN_B  = 256;
static const int NBLK    = (N_NODES + SCAN_B - 1) / SCAN_B;  // 391

// ---- scratch (__device__ globals; allocation is forbidden) ----
__device__ int    g_flags[2];        // [0]=which input is edge_index, [1]=is64
__device__ int    g_deg[N_NODES];
__device__ int    g_rowptr[N_NODES];
__device__ int    g_cursor[N_NODES];
__device__ float  g_dinv[N_NODES];
__device__ int    g_bsum[512];
__device__ int2   g_edge[N_EDGES];   // (src, bitcast(w)) in CSR-by-dst order
__device__ __half g_emb_h[N_NODES * 64];
__device__ __half g_x0_h[N_NODES * 64];
__device__ __half g_x1_h[N_NODES * 64];

// ---- input-ABI detection (device-side, graph-safe, no host sync) ---------
// Sample first 128 edge slots. int64 edges: odd words 0, even in [0,N).
// int32 edges: all words in [0,N). float emb bit patterns fail both.
__global__ void k_detect(const int* __restrict__ a, const int* __restrict__ b) {
    if (blockIdx.x != 0 || threadIdx.x != 0) return;
    const int* cand[2] = {a, b};
    int which = 1, is64 = 1;
    for (int c = 0; c < 2; c++) {
        const int* p = cand[c];
        bool ok64 = true, ok32 = true;
        for (int e = 0; e < 128; e++) {
            int lo = p[2 * e], hi = p[2 * e + 1];
            if (hi != 0 || lo < 0 || lo >= N_NODES) ok64 = false;
            if (lo < 0 || lo >= N_NODES || hi < 0 || hi >= N_NODES) ok32 = false;
        }
        if (ok64) { which = c; is64 = 1; break; }
        if (ok32) { which = c; is64 = 0; break; }
    }
    g_flags[0] = which;
    g_flags[1] = is64;
}

__device__ __forceinline__ const int* edge_ptr(const int* a, const int* b) {
    return g_flags[0] ? b : a;
}
__device__ __forceinline__ int load_node(const int* p, long long slot) {
    // slot in [0, 2*N_EDGES): logical edge_index element index
    int v = g_flags[1] ? p[2 * slot] : p[slot];
    return min(max(v, 0), N_NODES - 1);
}

// ---- CSR build -----------------------------------------------------------
__global__ void k_zero() {
    int i = blockIdx.x * blockDim.x + threadIdx.x;
    if (i < N_NODES) { g_deg[i] = 0; g_cursor[i] = 0; }
}

__global__ void k_hist(const int* __restrict__ a, const int* __restrict__ b) {
    int e = blockIdx.x * blockDim.x + threadIdx.x;
    if (e < N_EDGES) {
        const int* p = edge_ptr(a, b);
        atomicAdd(&g_deg[load_node(p, (long long)N_EDGES + e)], 1);
    }
}

__global__ void k_dinv() {
    int i = blockIdx.x * blockDim.x + threadIdx.x;
    if (i < N_NODES) {
        int d = g_deg[i];
        g_dinv[i] = (d > 0) ? rsqrtf((float)d) : 0.0f;
    }
}

// Block-local exclusive scan of g_deg -> g_rowptr; block totals -> g_bsum.
__global__ void k_scan_local() {
    __shared__ int wsum[8];
    int i = blockIdx.x * SCAN_B + threadIdx.x;
    int v = (i < N_NODES) ? g_deg[i] : 0;
    int lane = threadIdx.x & 31, wid = threadIdx.x >> 5;
    int x = v;
#pragma unroll
    for (int o = 1; o < 32; o <<= 1) {
        int y = __shfl_up_sync(0xffffffffu, x, o);
        if (lane >= o) x += y;
    }
    if (lane == 31) wsum[wid] = x;
    __syncthreads();
    if (wid == 0) {
        int s = (lane < 8) ? wsum[lane] : 0;
#pragma unroll
        for (int o = 1; o < 8; o <<= 1) {
            int y = __shfl_up_sync(0xffffffffu, s, o);
            if (lane >= o) s += y;
        }
        if (lane < 8) wsum[lane] = s;
    }
    __syncthreads();
    int incl = x + (wid > 0 ? wsum[wid - 1] : 0);
    if (i < N_NODES) g_rowptr[i] = incl - v;
    if (threadIdx.x == SCAN_B - 1) g_bsum[blockIdx.x] = incl;
}

__global__ void k_scan_bsum(int nb) {
    __shared__ int ws[16];
    int i = threadIdx.x;
    int v = (i < nb) ? g_bsum[i] : 0;
    int lane = i & 31, wid = i >> 5;
    int x = v;
#pragma unroll
    for (int o = 1; o < 32; o <<= 1) {
        int y = __shfl_up_sync(0xffffffffu, x, o);
        if (lane >= o) x += y;
    }
    if (lane == 31) ws[wid] = x;
    __syncthreads();
    if (wid == 0) {
        int s = (lane < 16) ? ws[lane] : 0;
#pragma unroll
        for (int o = 1; o < 16; o <<= 1) {
            int y = __shfl_up_sync(0xffffffffu, s, o);
            if (lane >= o) s += y;
        }
        if (lane < 16) ws[lane] = s;
    }
    __syncthreads();
    int excl = x - v + (wid > 0 ? ws[wid - 1] : 0);
    if (i < nb) g_bsum[i] = excl;
}

__global__ void k_scan_add() {
    int i = blockIdx.x * blockDim.x + threadIdx.x;
    if (i < N_NODES) g_rowptr[i] += g_bsum[i >> 8];  // SCAN_B == 256
}

__global__ void k_scatter(const int* __restrict__ a, const int* __restrict__ b) {
    int e = blockIdx.x * blockDim.x + threadIdx.x;
    if (e < N_EDGES) {
        const int* p = edge_ptr(a, b);
        int s = load_node(p, e);
        int d = load_node(p, (long long)N_EDGES + e);
        int pos = g_rowptr[d] + atomicAdd(&g_cursor[d], 1);
        float w = g_dinv[s] * g_dinv[d];
        g_edge[pos] = make_int2(s, __float_as_int(w));
    }
}

// ---- emb f32 -> fp16 copy (gather operand for layer 0) -------------------
__global__ void k_emb2h(const float2* __restrict__ a, const float2* __restrict__ b) {
    int i = blockIdx.x * blockDim.x + threadIdx.x;
    if (i >= N_NODES * 32) return;
    const float2* emb = g_flags[0] ? a : b;  // emb = the NON-edge input
    float2 v = emb[i];
    ((__half2*)g_x1_h)[0] = ((__half2*)g_x1_h)[0];  // no-op keeps symbol shape obvious
    ((__half2*)g_emb_h)[i] = __floats2half2_rn(v.x, v.y);
}

// ---- SpMM: warp per destination row, lane l owns dims [2l, 2l+1] ---------
// Gathered operand is fp16 (__half2 per lane, 128B per row); accumulation and
// the alpha-sum output stay f32. Edge (src,w) int2 pairs staged 32-wide
// through shared memory (LDS broadcast). One warp owns each output row.
// layer 0: xin = g_emb_h, xout = g_x0_h, out = 0.25*emb + 0.25*acc (fused init)
// layer 1: g_x0_h -> g_x1_h, out += 0.25*acc
// layer 2: g_x1_h -> (none),  out += 0.25*acc
__global__ void k_spmm(const float2* __restrict__ a, const float2* __restrict__ b,
                       float2* __restrict__ out, int layer) {
    __shared__ int2 sh[8][32];
    int wl   = threadIdx.x >> 5;
    int lane = threadIdx.x & 31;
    int row  = blockIdx.x * 8 + wl;
    if (row >= N_NODES) return;

    const __half2* xin;
    __half2* xout;
    if (layer == 0)      { xin = (const __half2*)g_emb_h; xout = (__half2*)g_x0_h; }
    else if (layer == 1) { xin = (const __half2*)g_x0_h;  xout = (__half2*)g_x1_h; }
    else                 { xin = (const __half2*)g_x1_h;  xout = nullptr;          }

    int start = g_rowptr[row];
    int cnt   = g_deg[row];
    float ax = 0.0f, ay = 0.0f;

    for (int base = 0; base < cnt; base += 32) {
        int rem = cnt - base;
        int m = rem < 32 ? rem : 32;
        if (lane < m) sh[wl][lane] = g_edge[start + base + lane];
        __syncwarp();
#pragma unroll 4
        for (int j = 0; j < m; j++) {
            int2  pr = sh[wl][j];
            float w  = __int_as_float(pr.y);
            float2 v = __half22float2(__ldg(&xin[pr.x * 32 + lane]));
            ax = fmaf(w, v.x, ax);
            ay = fmaf(w, v.y, ay);
        }
        __syncwarp();
    }

    int o = row * 32 + lane;
    if (xout) xout[o] = __floats2half2_rn(ax, ay);
    if (layer == 0) {
        const float2* emb = g_flags[0] ? a : b;
        float2 e = emb[o];
        out[o] = make_float2(0.25f * (e.x + ax), 0.25f * (e.y + ay));
    } else {
        float2 po = out[o];
        out[o] = make_float2(fmaf(0.25f, ax, po.x), fmaf(0.25f, ay, po.y));
    }
}

extern "C" void kernel_launch(void* const* d_in, const int* in_sizes, int n_in,
                              void* d_out, int out_size) {
    const void* p0 = d_in[0];
    const void* p1 = d_in[1];
    float* out = (float*)d_out;

    const int T  = 256;
    const int gN = (N_NODES + T - 1) / T;
    const int gE = (N_EDGES + T - 1) / T;

    // Resolve input ABI, then build CSR-by-dst + symmetric-norm weights
    // straight from the detected edge buffer (no conversion pass).
    k_detect    <<<1, 32>>>((const int*)p0, (const int*)p1);
    k_zero      <<<gN, T>>>();
    k_hist      <<<gE, T>>>((const int*)p0, (const int*)p1);
    k_dinv      <<<gN, T>>>();
    k_scan_local<<<NBLK, SCAN_B>>>();
    k_scan_bsum <<<1, 512>>>(NBLK);
    k_scan_add  <<<gN, T>>>();
    k_scatter   <<<gE, T>>>((const int*)p0, (const int*)p1);

    // fp16 copy of emb for layer-0 gathers.
    k_emb2h<<<(N_NODES * 32 + T - 1) / T, T>>>((const float2*)p0, (const float2*)p1);

    // 3 propagation layers; layer 0 also writes out = emb/4 (fused init).
    const int gS = (N_NODES + 7) / 8;  // 8 rows (warps) per 256-thread block
    k_spmm<<<gS, T>>>((const float2*)p0, (const float2*)p1, (float2*)out, 0);
    k_spmm<<<gS, T>>>((const float2*)p0, (const float2*)p1, (float2*)out, 1);
    k_spmm<<<gS, T>>>((const float2*)p0, (const float2*)p1, (float2*)out, 2);
}

// round 14
// speedup vs baseline: 1.3524x; 1.0507x over previous
#include <cuda_runtime.h>
#include <cuda_fp16.h>

// LightGCN embedding propagation (out = (emb + x1 + x2 + x3)/4,
// x_{k+1}[d] = sum_{e:dst=d} dinv[src]*dinv[dst] * x_k[src]).
//
// R10:
//  - SpMM: 16 lanes/row, LDG.64 (4 halves) per lane, 2 edges per warp-step,
//    final shfl(16) fold -> half the gather instructions, 2x MLP.
//  - alpha-sum deferred to layer 2 (single combine pass, no out RMW in L0/L1).
//  - dinv fused into scan_local; hist/scatter vectorized 2 edges/thread;
//    detect parallelized across a warp.

static const int N_NODES = 100000;
static const int N_EDGES = 3200000;   // even (required by 2-edge vectorization)
static const int SCAN_B  = 256;
static const int NBLK    = (N_NODES + SCAN_B - 1) / SCAN_B;  // 391

// ---- scratch (__device__ globals; allocation is forbidden) ----
__device__ int    g_flags[2];        // [0]=which input is edge_index, [1]=is64
__device__ int    g_deg[N_NODES];
__device__ int    g_rowptr[N_NODES];
__device__ int    g_cursor[N_NODES];
__device__ float  g_dinv[N_NODES];
__device__ int    g_bsum[512];
__device__ int2   g_edge[N_EDGES];   // (src, bitcast(w)) CSR-by-dst order
__device__ __half g_emb_h[N_NODES * 64];
__device__ __half g_x0_h[N_NODES * 64];
__device__ __half g_x1_h[N_NODES * 64];

// ---- input-ABI detection (one warp, graph-safe, no host sync) ------------
// int64 edges: odd words 0, even in [0,N). int32: all words in [0,N).
// float emb bit patterns fail both.
__global__ void k_detect(const int* __restrict__ a, const int* __restrict__ b) {
    int lane = threadIdx.x & 31;
    const int* cand[2] = {a, b};
    int which = 1, is64 = 1;
    for (int c = 0; c < 2; c++) {
        const int* p = cand[c];
        bool ok64 = true, ok32 = true;
#pragma unroll
        for (int t = 0; t < 4; t++) {
            int e = lane * 4 + t;
            int lo = p[2 * e], hi = p[2 * e + 1];
            if (hi != 0 || lo < 0 || lo >= N_NODES) ok64 = false;
            if (lo < 0 || lo >= N_NODES || hi < 0 || hi >= N_NODES) ok32 = false;
        }
        ok64 = __all_sync(0xffffffffu, ok64);
        ok32 = __all_sync(0xffffffffu, ok32);
        if (ok64) { which = c; is64 = 1; break; }
        if (ok32) { which = c; is64 = 0; break; }
    }
    if (lane == 0) { g_flags[0] = which; g_flags[1] = is64; }
}

__device__ __forceinline__ int clampn(int v) {
    return min(max(v, 0), N_NODES - 1);
}

// ---- CSR build -----------------------------------------------------------
__global__ void k_zero() {
    int i = blockIdx.x * blockDim.x + threadIdx.x;
    if (i < N_NODES) { g_deg[i] = 0; g_cursor[i] = 0; }
}

// 2 edges/thread; vector loads from the detected buffer.
__global__ void k_hist(const int* __restrict__ a, const int* __restrict__ b) {
    int e2 = 2 * (blockIdx.x * blockDim.x + threadIdx.x);
    if (e2 >= N_EDGES) return;
    const int* p = g_flags[0] ? b : a;
    int d0, d1;
    if (g_flags[1]) {
        int4 q = ((const int4*)p)[(N_EDGES + e2) >> 1];  // words 2N+2e2..+3
        d0 = q.x; d1 = q.z;
    } else {
        int2 q = ((const int2*)p)[(N_EDGES + e2) >> 1];  // words N+e2, N+e2+1
        d0 = q.x; d1 = q.y;
    }
    atomicAdd(&g_deg[clampn(d0)], 1);
    atomicAdd(&g_deg[clampn(d1)], 1);
}

// Block-local exclusive scan of g_deg -> g_rowptr; totals -> g_bsum; dinv fused.
__global__ void k_scan_local() {
    __shared__ int wsum[8];
    int i = blockIdx.x * SCAN_B + threadIdx.x;
    int v = (i < N_NODES) ? g_deg[i] : 0;
    if (i < N_NODES) g_dinv[i] = (v > 0) ? rsqrtf((float)v) : 0.0f;
    int lane = threadIdx.x & 31, wid = threadIdx.x >> 5;
    int x = v;
#pragma unroll
    for (int o = 1; o < 32; o <<= 1) {
        int y = __shfl_up_sync(0xffffffffu, x, o);
        if (lane >= o) x += y;
    }
    if (lane == 31) wsum[wid] = x;
    __syncthreads();
    if (wid == 0) {
        int s = (lane < 8) ? wsum[lane] : 0;
#pragma unroll
        for (int o = 1; o < 8; o <<= 1) {
            int y = __shfl_up_sync(0xffffffffu, s, o);
            if (lane >= o) s += y;
        }
        if (lane < 8) wsum[lane] = s;
    }
    __syncthreads();
    int incl = x + (wid > 0 ? wsum[wid - 1] : 0);
    if (i < N_NODES) g_rowptr[i] = incl - v;
    if (threadIdx.x == SCAN_B - 1) g_bsum[blockIdx.x] = incl;
}

__global__ void k_scan_bsum(int nb) {
    __shared__ int ws[16];
    int i = threadIdx.x;
    int v = (i < nb) ? g_bsum[i] : 0;
    int lane = i & 31, wid = i >> 5;
    int x = v;
#pragma unroll
    for (int o = 1; o < 32; o <<= 1) {
        int y = __shfl_up_sync(0xffffffffu, x, o);
        if (lane >= o) x += y;
    }
    if (lane == 31) ws[wid] = x;
    __syncthreads();
    if (wid == 0) {
        int s = (lane < 16) ? ws[lane] : 0;
#pragma unroll
        for (int o = 1; o < 16; o <<= 1) {
            int y = __shfl_up_sync(0xffffffffu, s, o);
            if (lane >= o) s += y;
        }
        if (lane < 16) ws[lane] = s;
    }
    __syncthreads();
    int excl = x - v + (wid > 0 ? ws[wid - 1] : 0);
    if (i < nb) g_bsum[i] = excl;
}

__global__ void k_scan_add() {
    int i = blockIdx.x * blockDim.x + threadIdx.x;
    if (i < N_NODES) g_rowptr[i] += g_bsum[i >> 8];  // SCAN_B == 256
}

// 2 edges/thread; vector loads for src and dst.
__global__ void k_scatter(const int* __restrict__ a, const int* __restrict__ b) {
    int e2 = 2 * (blockIdx.x * blockDim.x + threadIdx.x);
    if (e2 >= N_EDGES) return;
    const int* p = g_flags[0] ? b : a;
    int s0, s1, d0, d1;
    if (g_flags[1]) {
        int4 qs = ((const int4*)p)[e2 >> 1];                 // words 2e2..+3
        int4 qd = ((const int4*)p)[(N_EDGES + e2) >> 1];
        s0 = qs.x; s1 = qs.z; d0 = qd.x; d1 = qd.z;
    } else {
        int2 qs = ((const int2*)p)[e2 >> 1];
        int2 qd = ((const int2*)p)[(N_EDGES + e2) >> 1];
        s0 = qs.x; s1 = qs.y; d0 = qd.x; d1 = qd.y;
    }
    s0 = clampn(s0); s1 = clampn(s1); d0 = clampn(d0); d1 = clampn(d1);
    int pos0 = g_rowptr[d0] + atomicAdd(&g_cursor[d0], 1);
    g_edge[pos0] = make_int2(s0, __float_as_int(g_dinv[s0] * g_dinv[d0]));
    int pos1 = g_rowptr[d1] + atomicAdd(&g_cursor[d1], 1);
    g_edge[pos1] = make_int2(s1, __float_as_int(g_dinv[s1] * g_dinv[d1]));
}

// ---- emb f32 -> fp16 copy (gather operand for layer 0) -------------------
__global__ void k_emb2h(const float2* __restrict__ a, const float2* __restrict__ b) {
    int i = blockIdx.x * blockDim.x + threadIdx.x;
    if (i >= N_NODES * 32) return;
    const float2* emb = g_flags[0] ? a : b;  // emb = the NON-edge input
    float2 v = emb[i];
    ((__half2*)g_emb_h)[i] = __floats2half2_rn(v.x, v.y);
}

// ---- SpMM: warp per destination row, 2 edges per step --------------------
// 16 lanes cover a 64-dim fp16 row (uint2 = 4 halves per lane). Half-warp 0
// handles edge j, half-warp 1 handles edge j+1; accumulators folded once at
// the end via shfl_down(16). Edge (src,w) pairs staged 32-wide through shared.
// layer 0: emb_h -> x0_h         layer 1: x0_h -> x1_h
// layer 2: x1_h -> out = 0.25*(emb + x1 + x2 + acc)   (single combine pass)
__global__ void k_spmm(const float4* __restrict__ a, const float4* __restrict__ b,
                       float4* __restrict__ out, int layer) {
    __shared__ int2 sh[8][32];
    int wl   = threadIdx.x >> 5;
    int lane = threadIdx.x & 31;
    int row  = blockIdx.x * 8 + wl;
    if (row >= N_NODES) return;

    const uint2* xin;
    uint2* xout;
    if (layer == 0)      { xin = (const uint2*)g_emb_h; xout = (uint2*)g_x0_h; }
    else if (layer == 1) { xin = (const uint2*)g_x0_h;  xout = (uint2*)g_x1_h; }
    else                 { xin = (const uint2*)g_x1_h;  xout = nullptr;        }

    int start = g_rowptr[row];
    int cnt   = g_deg[row];
    int sub = lane >> 4, li = lane & 15;
    float4 acc = make_float4(0.f, 0.f, 0.f, 0.f);

    for (int base = 0; base < cnt; base += 32) {
        int m = min(cnt - base, 32);
        if (lane < m) sh[wl][lane] = g_edge[start + base + lane];
        __syncwarp();
#pragma unroll 4
        for (int j = 0; j < m; j += 2) {
            int jj = j + sub;
            int2 pr = sh[wl][min(jj, m - 1)];
            float w = (jj < m) ? __int_as_float(pr.y) : 0.0f;
            uint2 raw = __ldg(&xin[pr.x * 16 + li]);
            float2 v0 = __half22float2(*(const __half2*)&raw.x);
            float2 v1 = __half22float2(*(const __half2*)&raw.y);
            acc.x = fmaf(w, v0.x, acc.x);
            acc.y = fmaf(w, v0.y, acc.y);
            acc.z = fmaf(w, v1.x, acc.z);
            acc.w = fmaf(w, v1.y, acc.w);
        }
        __syncwarp();
    }

    // fold upper half-warp's edge subset into the lower half-warp
    acc.x += __shfl_down_sync(0xffffffffu, acc.x, 16);
    acc.y += __shfl_down_sync(0xffffffffu, acc.y, 16);
    acc.z += __shfl_down_sync(0xffffffffu, acc.z, 16);
    acc.w += __shfl_down_sync(0xffffffffu, acc.w, 16);

    if (lane < 16) {
        int o = row * 16 + li;
        if (xout) {
            uint2 pk;
            *(__half2*)&pk.x = __floats2half2_rn(acc.x, acc.y);
            *(__half2*)&pk.y = __floats2half2_rn(acc.z, acc.w);
            xout[o] = pk;
        } else {
            const float4* emb = g_flags[0] ? a : b;
            float4 e = emb[o];
            uint2 r1 = ((const uint2*)g_x0_h)[o];
            uint2 r2 = ((const uint2*)g_x1_h)[o];
            float2 x1a = __half22float2(*(const __half2*)&r1.x);
            float2 x1b = __half22float2(*(const __half2*)&r1.y);
            float2 x2a = __half22float2(*(const __half2*)&r2.x);
            float2 x2b = __half22float2(*(const __half2*)&r2.y);
            out[o] = make_float4(0.25f * (e.x + x1a.x + x2a.x + acc.x),
                                 0.25f * (e.y + x1a.y + x2a.y + acc.y),
                                 0.25f * (e.z + x1b.x + x2b.x + acc.z),
                                 0.25f * (e.w + x1b.y + x2b.y + acc.w));
        }
    }
}

extern "C" void kernel_launch(void* const* d_in, const int* in_sizes, int n_in,
                              void* d_out, int out_size) {
    const void* p0 = d_in[0];
    const void* p1 = d_in[1];
    float* out = (float*)d_out;

    const int T   = 256;
    const int gN  = (N_NODES + T - 1) / T;
    const int gE2 = (N_EDGES / 2 + T - 1) / T;

    k_detect    <<<1, 32>>>((const int*)p0, (const int*)p1);
    k_zero      <<<gN, T>>>();
    k_hist      <<<gE2, T>>>((const int*)p0, (const int*)p1);
    k_scan_local<<<NBLK, SCAN_B>>>();
    k_scan_bsum <<<1, 512>>>(NBLK);
    k_scan_add  <<<gN, T>>>();
    k_scatter   <<<gE2, T>>>((const int*)p0, (const int*)p1);

    k_emb2h<<<(N_NODES * 32 + T - 1) / T, T>>>((const float2*)p0, (const float2*)p1);

    const int gS = (N_NODES + 7) / 8;  // 8 rows (warps) per 256-thread block
    k_spmm<<<gS, T>>>((const float4*)p0, (const float4*)p1, (float4*)out, 0);
    k_spmm<<<gS, T>>>((const float4*)p0, (const float4*)p1, (float4*)out, 1);
    k_spmm<<<gS, T>>>((const float4*)p0, (const float4*)p1, (float4*)out, 2);
}

// round 16
// speedup vs baseline: 1.5317x; 1.1325x over previous
#include <cuda_runtime.h>
#include <cuda_fp16.h>

// LightGCN embedding propagation (out = (emb + x1 + x2 + x3)/4,
// x_{k+1}[d] = sum_{e:dst=d} dinv[src]*dinv[dst] * x_k[src]).
//
// R15:
//  - SpMM: 4 edges per warp-step; 8 lanes x uint4 (8 halves) per edge row;
//    LDG.128 gathers; two-stage shfl fold. Halves LDG + issue count again.
//  - detect fused with zero; hist fused with emb->fp16 copy (overlap).
//  - scatter post-increments rowptr directly (no cursor array).

static const int N_NODES = 100000;
static const int N_EDGES = 3200000;   // even
static const int SCAN_B  = 256;
static const int NBLK    = (N_NODES + SCAN_B - 1) / SCAN_B;  // 391

// ---- scratch (__device__ globals; allocation is forbidden) ----
__device__ int    g_flags[2];        // [0]=which input is edge_index, [1]=is64
__device__ int    g_deg[N_NODES];
__device__ int    g_rowptr[N_NODES];
__device__ float  g_dinv[N_NODES];
__device__ int    g_bsum[512];
__device__ int2   g_edge[N_EDGES];   // (src, bitcast(w)) CSR-by-dst order
__device__ __half g_emb_h[N_NODES * 64];
__device__ __half g_x0_h[N_NODES * 64];
__device__ __half g_x1_h[N_NODES * 64];

__device__ __forceinline__ int clampn(int v) {
    return min(max(v, 0), N_NODES - 1);
}

// ---- detect (warp 0 of block 0) + zero deg, one kernel -------------------
// int64 edges: odd words 0, even in [0,N). int32: all words in [0,N).
// float emb bit patterns fail both tests.
__global__ void k_detect_zero(const int* __restrict__ a, const int* __restrict__ b) {
    if (blockIdx.x == 0 && threadIdx.x < 32) {
        int lane = threadIdx.x;
        const int* cand[2] = {a, b};
        int which = 1, is64 = 1;
        for (int c = 0; c < 2; c++) {
            const int* p = cand[c];
            bool ok64 = true, ok32 = true;
#pragma unroll
            for (int t = 0; t < 4; t++) {
                int e = lane * 4 + t;
                int lo = p[2 * e], hi = p[2 * e + 1];
                if (hi != 0 || lo < 0 || lo >= N_NODES) ok64 = false;
                if (lo < 0 || lo >= N_NODES || hi < 0 || hi >= N_NODES) ok32 = false;
            }
            ok64 = __all_sync(0xffffffffu, ok64);
            ok32 = __all_sync(0xffffffffu, ok32);
            if (ok64) { which = c; is64 = 1; break; }
            if (ok32) { which = c; is64 = 0; break; }
        }
        if (lane == 0) { g_flags[0] = which; g_flags[1] = is64; }
    }
    int i = blockIdx.x * blockDim.x + threadIdx.x;
    if (i < N_NODES) g_deg[i] = 0;
}

// ---- hist (2 edges/thread) + emb->fp16 copy, one kernel (overlapped) -----
static const int HIST_BLOCKS = (N_EDGES / 2 + 255) / 256;        // 6250
static const int EMBH_BLOCKS = (N_NODES * 32 + 255) / 256;       // 12500

__global__ void k_hist_emb2h(const int* __restrict__ a, const int* __restrict__ b,
                             const float2* __restrict__ fa, const float2* __restrict__ fb) {
    int blk = blockIdx.x;
    if (blk < HIST_BLOCKS) {
        int e2 = 2 * (blk * blockDim.x + threadIdx.x);
        if (e2 >= N_EDGES) return;
        const int* p = g_flags[0] ? b : a;
        int d0, d1;
        if (g_flags[1]) {
            int4 q = ((const int4*)p)[(N_EDGES + e2) >> 1];
            d0 = q.x; d1 = q.z;
        } else {
            int2 q = ((const int2*)p)[(N_EDGES + e2) >> 1];
            d0 = q.x; d1 = q.y;
        }
        atomicAdd(&g_deg[clampn(d0)], 1);
        atomicAdd(&g_deg[clampn(d1)], 1);
    } else {
        int i = (blk - HIST_BLOCKS) * blockDim.x + threadIdx.x;
        if (i >= N_NODES * 32) return;
        const float2* emb = g_flags[0] ? fa : fb;  // emb = the NON-edge input
        float2 v = emb[i];
        ((__half2*)g_emb_h)[i] = __floats2half2_rn(v.x, v.y);
    }
}

// ---- scan: block-local exclusive scan of deg -> rowptr; dinv fused -------
__global__ void k_scan_local() {
    __shared__ int wsum[8];
    int i = blockIdx.x * SCAN_B + threadIdx.x;
    int v = (i < N_NODES) ? g_deg[i] : 0;
    if (i < N_NODES) g_dinv[i] = (v > 0) ? rsqrtf((float)v) : 0.0f;
    int lane = threadIdx.x & 31, wid = threadIdx.x >> 5;
    int x = v;
#pragma unroll
    for (int o = 1; o < 32; o <<= 1) {
        int y = __shfl_up_sync(0xffffffffu, x, o);
        if (lane >= o) x += y;
    }
    if (lane == 31) wsum[wid] = x;
    __syncthreads();
    if (wid == 0) {
        int s = (lane < 8) ? wsum[lane] : 0;
#pragma unroll
        for (int o = 1; o < 8; o <<= 1) {
            int y = __shfl_up_sync(0xffffffffu, s, o);
            if (lane >= o) s += y;
        }
        if (lane < 8) wsum[lane] = s;
    }
    __syncthreads();
    int incl = x + (wid > 0 ? wsum[wid - 1] : 0);
    if (i < N_NODES) g_rowptr[i] = incl - v;
    if (threadIdx.x == SCAN_B - 1) g_bsum[blockIdx.x] = incl;
}

__global__ void k_scan_bsum(int nb) {
    __shared__ int ws[16];
    int i = threadIdx.x;
    int v = (i < nb) ? g_bsum[i] : 0;
    int lane = i & 31, wid = i >> 5;
    int x = v;
#pragma unroll
    for (int o = 1; o < 32; o <<= 1) {
        int y = __shfl_up_sync(0xffffffffu, x, o);
        if (lane >= o) x += y;
    }
    if (lane == 31) ws[wid] = x;
    __syncthreads();
    if (wid == 0) {
        int s = (lane < 16) ? ws[lane] : 0;
#pragma unroll
        for (int o = 1; o < 16; o <<= 1) {
            int y = __shfl_up_sync(0xffffffffu, s, o);
            if (lane >= o) s += y;
        }
        if (lane < 16) ws[lane] = s;
    }
    __syncthreads();
    int excl = x - v + (wid > 0 ? ws[wid - 1] : 0);
    if (i < nb) g_bsum[i] = excl;
}

__global__ void k_scan_add() {
    int i = blockIdx.x * blockDim.x + threadIdx.x;
    if (i < N_NODES) g_rowptr[i] += g_bsum[i >> 8];  // SCAN_B == 256
}

// ---- scatter: post-increment rowptr itself (after this, rowptr = row end) -
__global__ void k_scatter(const int* __restrict__ a, const int* __restrict__ b) {
    int e2 = 2 * (blockIdx.x * blockDim.x + threadIdx.x);
    if (e2 >= N_EDGES) return;
    const int* p = g_flags[0] ? b : a;
    int s0, s1, d0, d1;
    if (g_flags[1]) {
        int4 qs = ((const int4*)p)[e2 >> 1];
        int4 qd = ((const int4*)p)[(N_EDGES + e2) >> 1];
        s0 = qs.x; s1 = qs.z; d0 = qd.x; d1 = qd.z;
    } else {
        int2 qs = ((const int2*)p)[e2 >> 1];
        int2 qd = ((const int2*)p)[(N_EDGES + e2) >> 1];
        s0 = qs.x; s1 = qs.y; d0 = qd.x; d1 = qd.y;
    }
    s0 = clampn(s0); s1 = clampn(s1); d0 = clampn(d0); d1 = clampn(d1);
    int pos0 = atomicAdd(&g_rowptr[d0], 1);
    g_edge[pos0] = make_int2(s0, __float_as_int(g_dinv[s0] * g_dinv[d0]));
    int pos1 = atomicAdd(&g_rowptr[d1], 1);
    g_edge[pos1] = make_int2(s1, __float_as_int(g_dinv[s1] * g_dinv[d1]));
}

// ---- SpMM: warp per destination row, 4 edges per step --------------------
// 8 lanes cover a 64-half row (uint4 = 8 halves/lane). Four 8-lane subgroups
// handle edges j..j+3; folds via shfl_down(16) then shfl_down(8).
// After scatter, rowptr[row] = row END; start = end - deg.
// layer 0: emb_h -> x0_h   layer 1: x0_h -> x1_h
// layer 2: x1_h -> out = 0.25*(emb + x1 + x2 + acc)
__global__ void k_spmm(const float4* __restrict__ a, const float4* __restrict__ b,
                       float4* __restrict__ out, int layer) {
    __shared__ int2 sh[8][32];
    int wl   = threadIdx.x >> 5;
    int lane = threadIdx.x & 31;
    int row  = blockIdx.x * 8 + wl;
    if (row >= N_NODES) return;

    const uint4* xin;
    uint4* xout;
    if (layer == 0)      { xin = (const uint4*)g_emb_h; xout = (uint4*)g_x0_h; }
    else if (layer == 1) { xin = (const uint4*)g_x0_h;  xout = (uint4*)g_x1_h; }
    else                 { xin = (const uint4*)g_x1_h;  xout = nullptr;        }

    int cnt   = g_deg[row];
    int start = g_rowptr[row] - cnt;   // rowptr holds row end after scatter
    int sub = lane >> 3, li = lane & 7;
    float4 accA = make_float4(0.f, 0.f, 0.f, 0.f);
    float4 accB = make_float4(0.f, 0.f, 0.f, 0.f);

    for (int base = 0; base < cnt; base += 32) {
        int m = min(cnt - base, 32);
        if (lane < m) sh[wl][lane] = g_edge[start + base + lane];
        __syncwarp();
#pragma unroll 2
        for (int j = 0; j < m; j += 4) {
            int jj = j + sub;
            int2 pr = sh[wl][min(jj, m - 1)];
            float w = (jj < m) ? __int_as_float(pr.y) : 0.0f;
            uint4 raw = __ldg(&xin[pr.x * 8 + li]);
            float2 v0 = __half22float2(*(const __half2*)&raw.x);
            float2 v1 = __half22float2(*(const __half2*)&raw.y);
            float2 v2 = __half22float2(*(const __half2*)&raw.z);
            float2 v3 = __half22float2(*(const __half2*)&raw.w);
            accA.x = fmaf(w, v0.x, accA.x);
            accA.y = fmaf(w, v0.y, accA.y);
            accA.z = fmaf(w, v1.x, accA.z);
            accA.w = fmaf(w, v1.y, accA.w);
            accB.x = fmaf(w, v2.x, accB.x);
            accB.y = fmaf(w, v2.y, accB.y);
            accB.z = fmaf(w, v3.x, accB.z);
            accB.w = fmaf(w, v3.y, accB.w);
        }
        __syncwarp();
    }

    // fold 4 subgroups -> subgroup 0 (lanes 0..7)
#pragma unroll
    for (int off = 16; off >= 8; off >>= 1) {
        accA.x += __shfl_down_sync(0xffffffffu, accA.x, off);
        accA.y += __shfl_down_sync(0xffffffffu, accA.y, off);
        accA.z += __shfl_down_sync(0xffffffffu, accA.z, off);
        accA.w += __shfl_down_sync(0xffffffffu, accA.w, off);
        accB.x += __shfl_down_sync(0xffffffffu, accB.x, off);
        accB.y += __shfl_down_sync(0xffffffffu, accB.y, off);
        accB.z += __shfl_down_sync(0xffffffffu, accB.z, off);
        accB.w += __shfl_down_sync(0xffffffffu, accB.w, off);
    }

    if (lane < 8) {
        int ho = row * 8 + li;
        if (xout) {
            uint4 pk;
            *(__half2*)&pk.x = __floats2half2_rn(accA.x, accA.y);
            *(__half2*)&pk.y = __floats2half2_rn(accA.z, accA.w);
            *(__half2*)&pk.z = __floats2half2_rn(accB.x, accB.y);
            *(__half2*)&pk.w = __floats2half2_rn(accB.z, accB.w);
            xout[ho] = pk;
        } else {
            const float4* emb = g_flags[0] ? a : b;
            uint4 r1 = ((const uint4*)g_x0_h)[ho];
            uint4 r2 = ((const uint4*)g_x1_h)[ho];
            float4 e0 = emb[row * 16 + 2 * li];
            float4 e1 = emb[row * 16 + 2 * li + 1];
            float2 p0 = __half22float2(*(const __half2*)&r1.x);
            float2 p1 = __half22float2(*(const __half2*)&r1.y);
            float2 p2 = __half22float2(*(const __half2*)&r1.z);
            float2 p3 = __half22float2(*(const __half2*)&r1.w);
            float2 q0 = __half22float2(*(const __half2*)&r2.x);
            float2 q1 = __half22float2(*(const __half2*)&r2.y);
            float2 q2 = __half22float2(*(const __half2*)&r2.z);
            float2 q3 = __half22float2(*(const __half2*)&r2.w);
            out[row * 16 + 2 * li] =
                make_float4(0.25f * (e0.x + p0.x + q0.x + accA.x),
                            0.25f * (e0.y + p0.y + q0.y + accA.y),
                            0.25f * (e0.z + p1.x + q1.x + accA.z),
                            0.25f * (e0.w + p1.y + q1.y + accA.w));
            out[row * 16 + 2 * li + 1] =
                make_float4(0.25f * (e1.x + p2.x + q2.x + accB.x),
                            0.25f * (e1.y + p2.y + q2.y + accB.y),
                            0.25f * (e1.z + p3.x + q3.x + accB.z),
                            0.25f * (e1.w + p3.y + q3.y + accB.w));
        }
    }
}

extern "C" void kernel_launch(void* const* d_in, const int* in_sizes, int n_in,
                              void* d_out, int out_size) {
    const void* p0 = d_in[0];
    const void* p1 = d_in[1];
    float* out = (float*)d_out;

    const int T   = 256;
    const int gN  = (N_NODES + T - 1) / T;
    const int gE2 = (N_EDGES / 2 + T - 1) / T;

    k_detect_zero<<<gN, T>>>((const int*)p0, (const int*)p1);
    k_hist_emb2h <<<HIST_BLOCKS + EMBH_BLOCKS, T>>>(
        (const int*)p0, (const int*)p1, (const float2*)p0, (const float2*)p1);
    k_scan_local <<<NBLK, SCAN_B>>>();
    k_scan_bsum  <<<1, 512>>>(NBLK);
    k_scan_add   <<<gN, T>>>();
    k_scatter    <<<gE2, T>>>((const int*)p0, (const int*)p1);

    const int gS = (N_NODES + 7) / 8;  // 8 rows (warps) per 256-thread block
    k_spmm<<<gS, T>>>((const float4*)p0, (const float4*)p1, (float4*)out, 0);
    k_spmm<<<gS, T>>>((const float4*)p0, (const float4*)p1, (float4*)out, 1);
    k_spmm<<<gS, T>>>((const float4*)p0, (const float4*)p1, (float4*)out, 2);
}

// round 17
// speedup vs baseline: 1.6958x; 1.1072x over previous
#include <cuda_runtime.h>
#include <cuda_fp16.h>

// LightGCN embedding propagation (out = (emb + x1 + x2 + x3)/4,
// x_{k+1}[d] = sum_{e:dst=d} dinv[src]*dinv[dst] * x_k[src]).
//
// R16:
//  - SpMM: no shared staging. Each 8-lane subgroup broadcast-loads its edge
//    int2 directly (1 wavefront), then LDG.128 gathers the fp16 row. Flat
//    loop -> compiler front-batches loads, higher MLP, no syncwarp.
//  - scan fixup collapsed to one kernel (prefix SUM of block totals).

static const int N_NODES = 100000;
static const int N_EDGES = 3200000;   // even
static const int SCAN_B  = 256;
static const int NBLK    = (N_NODES + SCAN_B - 1) / SCAN_B;  // 391

// ---- scratch (__device__ globals; allocation is forbidden) ----
__device__ int    g_flags[2];        // [0]=which input is edge_index, [1]=is64
__device__ int    g_deg[N_NODES];
__device__ int    g_rowptr[N_NODES];
__device__ float  g_dinv[N_NODES];
__device__ int    g_bsum[512];
__device__ int2   g_edge[N_EDGES];   // (src, bitcast(w)) CSR-by-dst order
__device__ __half g_emb_h[N_NODES * 64];
__device__ __half g_x0_h[N_NODES * 64];
__device__ __half g_x1_h[N_NODES * 64];

__device__ __forceinline__ int clampn(int v) {
    return min(max(v, 0), N_NODES - 1);
}

// ---- detect (warp 0 of block 0) + zero deg, one kernel -------------------
// int64 edges: odd words 0, even in [0,N). int32: all words in [0,N).
// float emb bit patterns fail both tests.
__global__ void k_detect_zero(const int* __restrict__ a, const int* __restrict__ b) {
    if (blockIdx.x == 0 && threadIdx.x < 32) {
        int lane = threadIdx.x;
        const int* cand[2] = {a, b};
        int which = 1, is64 = 1;
        for (int c = 0; c < 2; c++) {
            const int* p = cand[c];
            bool ok64 = true, ok32 = true;
#pragma unroll
            for (int t = 0; t < 4; t++) {
                int e = lane * 4 + t;
                int lo = p[2 * e], hi = p[2 * e + 1];
                if (hi != 0 || lo < 0 || lo >= N_NODES) ok64 = false;
                if (lo < 0 || lo >= N_NODES || hi < 0 || hi >= N_NODES) ok32 = false;
            }
            ok64 = __all_sync(0xffffffffu, ok64);
            ok32 = __all_sync(0xffffffffu, ok32);
            if (ok64) { which = c; is64 = 1; break; }
            if (ok32) { which = c; is64 = 0; break; }
        }
        if (lane == 0) { g_flags[0] = which; g_flags[1] = is64; }
    }
    int i = blockIdx.x * blockDim.x + threadIdx.x;
    if (i < N_NODES) g_deg[i] = 0;
}

// ---- hist (2 edges/thread) + emb->fp16 copy, one kernel (overlapped) -----
static const int HIST_BLOCKS = (N_EDGES / 2 + 255) / 256;        // 6250
static const int EMBH_BLOCKS = (N_NODES * 32 + 255) / 256;       // 12500

__global__ void k_hist_emb2h(const int* __restrict__ a, const int* __restrict__ b,
                             const float2* __restrict__ fa, const float2* __restrict__ fb) {
    int blk = blockIdx.x;
    if (blk < HIST_BLOCKS) {
        int e2 = 2 * (blk * blockDim.x + threadIdx.x);
        if (e2 >= N_EDGES) return;
        const int* p = g_flags[0] ? b : a;
        int d0, d1;
        if (g_flags[1]) {
            int4 q = ((const int4*)p)[(N_EDGES + e2) >> 1];
            d0 = q.x; d1 = q.z;
        } else {
            int2 q = ((const int2*)p)[(N_EDGES + e2) >> 1];
            d0 = q.x; d1 = q.y;
        }
        atomicAdd(&g_deg[clampn(d0)], 1);
        atomicAdd(&g_deg[clampn(d1)], 1);
    } else {
        int i = (blk - HIST_BLOCKS) * blockDim.x + threadIdx.x;
        if (i >= N_NODES * 32) return;
        const float2* emb = g_flags[0] ? fa : fb;  // emb = the NON-edge input
        float2 v = emb[i];
        ((__half2*)g_emb_h)[i] = __floats2half2_rn(v.x, v.y);
    }
}

// ---- scan: block-local exclusive scan of deg -> rowptr; dinv fused -------
__global__ void k_scan_local() {
    __shared__ int wsum[8];
    int i = blockIdx.x * SCAN_B + threadIdx.x;
    int v = (i < N_NODES) ? g_deg[i] : 0;
    if (i < N_NODES) g_dinv[i] = (v > 0) ? rsqrtf((float)v) : 0.0f;
    int lane = threadIdx.x & 31, wid = threadIdx.x >> 5;
    int x = v;
#pragma unroll
    for (int o = 1; o < 32; o <<= 1) {
        int y = __shfl_up_sync(0xffffffffu, x, o);
        if (lane >= o) x += y;
    }
    if (lane == 31) wsum[wid] = x;
    __syncthreads();
    if (wid == 0) {
        int s = (lane < 8) ? wsum[lane] : 0;
#pragma unroll
        for (int o = 1; o < 8; o <<= 1) {
            int y = __shfl_up_sync(0xffffffffu, s, o);
            if (lane >= o) s += y;
        }
        if (lane < 8) wsum[lane] = s;
    }
    __syncthreads();
    int incl = x + (wid > 0 ? wsum[wid - 1] : 0);
    if (i < N_NODES) g_rowptr[i] = incl - v;
    if (threadIdx.x == SCAN_B - 1) g_bsum[blockIdx.x] = incl;
}

// ---- scan finish: rowptr[i] += sum of preceding block totals -------------
// Each block needs only the SUM over g_bsum[0..blockIdx.x), reduced by its
// own 256 threads (<=391 values, L2-hot). Replaces scan_bsum + scan_add.
__global__ void k_scan_finish() {
    __shared__ int red[8];
    int bi = blockIdx.x;
    int t  = threadIdx.x;
    int part = 0;
    for (int k = t; k < bi; k += SCAN_B) part += g_bsum[k];
    // block reduce
    int lane = t & 31, wid = t >> 5;
#pragma unroll
    for (int o = 16; o > 0; o >>= 1) part += __shfl_down_sync(0xffffffffu, part, o);
    if (lane == 0) red[wid] = part;
    __syncthreads();
    if (wid == 0) {
        int s = (lane < 8) ? red[lane] : 0;
#pragma unroll
        for (int o = 4; o > 0; o >>= 1) s += __shfl_down_sync(0xffffffffu, s, o);
        if (lane == 0) red[0] = s;
    }
    __syncthreads();
    int base = red[0];
    int i = bi * SCAN_B + t;
    if (i < N_NODES) g_rowptr[i] += base;
}

// ---- scatter: post-increment rowptr itself (after this, rowptr = row end) -
__global__ void k_scatter(const int* __restrict__ a, const int* __restrict__ b) {
    int e2 = 2 * (blockIdx.x * blockDim.x + threadIdx.x);
    if (e2 >= N_EDGES) return;
    const int* p = g_flags[0] ? b : a;
    int s0, s1, d0, d1;
    if (g_flags[1]) {
        int4 qs = ((const int4*)p)[e2 >> 1];
        int4 qd = ((const int4*)p)[(N_EDGES + e2) >> 1];
        s0 = qs.x; s1 = qs.z; d0 = qd.x; d1 = qd.z;
    } else {
        int2 qs = ((const int2*)p)[e2 >> 1];
        int2 qd = ((const int2*)p)[(N_EDGES + e2) >> 1];
        s0 = qs.x; s1 = qs.y; d0 = qd.x; d1 = qd.y;
    }
    s0 = clampn(s0); s1 = clampn(s1); d0 = clampn(d0); d1 = clampn(d1);
    int pos0 = atomicAdd(&g_rowptr[d0], 1);
    g_edge[pos0] = make_int2(s0, __float_as_int(g_dinv[s0] * g_dinv[d0]));
    int pos1 = atomicAdd(&g_rowptr[d1], 1);
    g_edge[pos1] = make_int2(s1, __float_as_int(g_dinv[s1] * g_dinv[d1]));
}

// ---- SpMM: warp per destination row, 4 edges per step, no staging --------
// 8 lanes cover a 64-half row (uint4 = 8 halves/lane). Subgroup s handles
// edges j ≡ s (mod 4); each subgroup broadcast-loads its edge int2 directly
// (same address across 8 lanes -> 1 wavefront; 4 consecutive int2 per warp).
// Flat loop: no LDS, no syncwarp, loads front-batchable by ptxas.
// After scatter, rowptr[row] = row END; start = end - deg.
// layer 0: emb_h -> x0_h   layer 1: x0_h -> x1_h
// layer 2: x1_h -> out = 0.25*(emb + x1 + x2 + acc)
__global__ void k_spmm(const float4* __restrict__ a, const float4* __restrict__ b,
                       float4* __restrict__ out, int layer) {
    int wl   = threadIdx.x >> 5;
    int lane = threadIdx.x & 31;
    int row  = blockIdx.x * 8 + wl;
    if (row >= N_NODES) return;

    const uint4* xin;
    uint4* xout;
    if (layer == 0)      { xin = (const uint4*)g_emb_h; xout = (uint4*)g_x0_h; }
    else if (layer == 1) { xin = (const uint4*)g_x0_h;  xout = (uint4*)g_x1_h; }
    else                 { xin = (const uint4*)g_x1_h;  xout = nullptr;        }

    int cnt   = g_deg[row];
    int start = g_rowptr[row] - cnt;   // rowptr holds row end after scatter
    int sub = lane >> 3, li = lane & 7;
    float4 accA = make_float4(0.f, 0.f, 0.f, 0.f);
    float4 accB = make_float4(0.f, 0.f, 0.f, 0.f);

#pragma unroll 2
    for (int j = sub; j < cnt; j += 4) {
        int2 pr = __ldg(&g_edge[start + j]);
        float w = __int_as_float(pr.y);
        uint4 raw = __ldg(&xin[pr.x * 8 + li]);
        float2 v0 = __half22float2(*(const __half2*)&raw.x);
        float2 v1 = __half22float2(*(const __half2*)&raw.y);
        float2 v2 = __half22float2(*(const __half2*)&raw.z);
        float2 v3 = __half22float2(*(const __half2*)&raw.w);
        accA.x = fmaf(w, v0.x, accA.x);
        accA.y = fmaf(w, v0.y, accA.y);
        accA.z = fmaf(w, v1.x, accA.z);
        accA.w = fmaf(w, v1.y, accA.w);
        accB.x = fmaf(w, v2.x, accB.x);
        accB.y = fmaf(w, v2.y, accB.y);
        accB.z = fmaf(w, v3.x, accB.z);
        accB.w = fmaf(w, v3.y, accB.w);
    }

    // fold 4 subgroups -> subgroup 0 (lanes 0..7)
#pragma unroll
    for (int off = 16; off >= 8; off >>= 1) {
        accA.x += __shfl_down_sync(0xffffffffu, accA.x, off);
        accA.y += __shfl_down_sync(0xffffffffu, accA.y, off);
        accA.z += __shfl_down_sync(0xffffffffu, accA.z, off);
        accA.w += __shfl_down_sync(0xffffffffu, accA.w, off);
        accB.x += __shfl_down_sync(0xffffffffu, accB.x, off);
        accB.y += __shfl_down_sync(0xffffffffu, accB.y, off);
        accB.z += __shfl_down_sync(0xffffffffu, accB.z, off);
        accB.w += __shfl_down_sync(0xffffffffu, accB.w, off);
    }

    if (lane < 8) {
        int ho = row * 8 + li;
        if (xout) {
            uint4 pk;
            *(__half2*)&pk.x = __floats2half2_rn(accA.x, accA.y);
            *(__half2*)&pk.y = __floats2half2_rn(accA.z, accA.w);
            *(__half2*)&pk.z = __floats2half2_rn(accB.x, accB.y);
            *(__half2*)&pk.w = __floats2half2_rn(accB.z, accB.w);
            xout[ho] = pk;
        } else {
            const float4* emb = g_flags[0] ? a : b;
            uint4 r1 = ((const uint4*)g_x0_h)[ho];
            uint4 r2 = ((const uint4*)g_x1_h)[ho];
            float4 e0 = emb[row * 16 + 2 * li];
            float4 e1 = emb[row * 16 + 2 * li + 1];
            float2 p0 = __half22float2(*(const __half2*)&r1.x);
            float2 p1 = __half22float2(*(const __half2*)&r1.y);
            float2 p2 = __half22float2(*(const __half2*)&r1.z);
            float2 p3 = __half22float2(*(const __half2*)&r1.w);
            float2 q0 = __half22float2(*(const __half2*)&r2.x);
            float2 q1 = __half22float2(*(const __half2*)&r2.y);
            float2 q2 = __half22float2(*(const __half2*)&r2.z);
            float2 q3 = __half22float2(*(const __half2*)&r2.w);
            out[row * 16 + 2 * li] =
                make_float4(0.25f * (e0.x + p0.x + q0.x + accA.x),
                            0.25f * (e0.y + p0.y + q0.y + accA.y),
                            0.25f * (e0.z + p1.x + q1.x + accA.z),
                            0.25f * (e0.w + p1.y + q1.y + accA.w));
            out[row * 16 + 2 * li + 1] =
                make_float4(0.25f * (e1.x + p2.x + q2.x + accB.x),
                            0.25f * (e1.y + p2.y + q2.y + accB.y),
                            0.25f * (e1.z + p3.x + q3.x + accB.z),
                            0.25f * (e1.w + p3.y + q3.y + accB.w));
        }
    }
}

extern "C" void kernel_launch(void* const* d_in, const int* in_sizes, int n_in,
                              void* d_out, int out_size) {
    const void* p0 = d_in[0];
    const void* p1 = d_in[1];
    float* out = (float*)d_out;

    const int T   = 256;
    const int gN  = (N_NODES + T - 1) / T;
    const int gE2 = (N_EDGES / 2 + T - 1) / T;

    k_detect_zero<<<gN, T>>>((const int*)p0, (const int*)p1);
    k_hist_emb2h <<<HIST_BLOCKS + EMBH_BLOCKS, T>>>(
        (const int*)p0, (const int*)p1, (const float2*)p0, (const float2*)p1);
    k_scan_local <<<NBLK, SCAN_B>>>();
    k_scan_finish<<<NBLK, SCAN_B>>>();
    k_scatter    <<<gE2, T>>>((const int*)p0, (const int*)p1);

    const int gS = (N_NODES + 7) / 8;  // 8 rows (warps) per 256-thread block
    k_spmm<<<gS, T>>>((const float4*)p0, (const float4*)p1, (float4*)out, 0);
    k_spmm<<<gS, T>>>((const float4*)p0, (const float4*)p1, (float4*)out, 1);
    k_spmm<<<gS, T>>>((const float4*)p0, (const float4*)p1, (float4*)out, 2);
}